// round 3
// baseline (speedup 1.0000x reference)
#include <cuda_runtime.h>

// QPSK modulator: bits (256,16384) int32 -> Gray QPSK -> x16 zero-stuff
// (offset 8) -> RRC (K=128) -> out (256, 131072, 2) float32.
//
// Polyphase: y[16q+p] = sum_{i=0..7} sym[q+jmin+i] * rrc[k0+16i],
//   k0 = (71-p)&15, jmin = (p<=7) ? -4 : -3, scaled by sqrt(16).
// sqrt(16)/sqrt(2) folded into taps so symbols are +-1.
//
// R3: each thread owns a FIXED phase QUAD p0..p0+3 (p0 in {0,4,8,12}).
// All 4 phases share the same symbol window and flag -> 8 LDS.64 feed
// 4 complex outputs (32 FFMA2), then 2 streaming STG.128. Taps live in
// 32 duplicated f32x2 registers, loaded once.

#define B_ROWS     256
#define NUM_BITS   16384
#define NS         8192
#define SPS        16
#define UP_LEN     (NS * SPS)
#define K_TAPS     128

#define SYMS_PER_BLOCK   128
#define OUTS_PER_BLOCK   (SYMS_PER_BLOCK * SPS)   // 2048 complex
#define THREADS          256
#define HALO_L           4
#define SYM_TILE         (SYMS_PER_BLOCK + 8)     // 136

typedef unsigned long long ull;

__device__ __forceinline__ ull pack2(float lo, float hi) {
    ull v;
    asm("mov.b64 %0, {%1, %2};" : "=l"(v) : "f"(lo), "f"(hi));
    return v;
}

__device__ __forceinline__ void fma2(ull& acc, ull a, ull b) {
    asm("fma.rn.f32x2 %0, %1, %2, %0;" : "+l"(acc) : "l"(a), "l"(b));
}

__device__ __forceinline__ void stcs2(ull* p, ull lo, ull hi) {
    asm volatile("st.global.cs.v2.u64 [%0], {%1, %2};"
                 :: "l"(p), "l"(lo), "l"(hi) : "memory");
}

__global__ __launch_bounds__(THREADS, 2)
void qpsk_mod_kernel(const int* __restrict__ bits,
                     const float* __restrict__ rrc,
                     ull* __restrict__ out2)   // out viewed as u64 (1 complex each)
{
    __shared__ float  s_rrc[K_TAPS];
    __shared__ float2 s_sym[SYM_TILE];

    const int tid  = threadIdx.x;
    const int tile = blockIdx.x;          // 0..63
    const int row  = blockIdx.y;          // 0..255
    const int q0   = tile * SYMS_PER_BLOCK;

    // Stage taps, pre-scaled by sqrt(SPS)/sqrt(2) = 2*sqrt(2)
    if (tid < K_TAPS)
        s_rrc[tid] = rrc[tid] * 2.82842712474619f;

    // Stage symbols (+-1) with halo; zero outside [0, NS)
    const int2* bits2 = (const int2*)(bits + (long long)row * NUM_BITS);
    for (int s = tid; s < SYM_TILE; s += THREADS) {
        int g = q0 - HALO_L + s;
        float re = 0.f, im = 0.f;
        if (g >= 0 && g < NS) {
            int2 bb = bits2[g];   // bb.x = bits[2g] (-> imag), bb.y = bits[2g+1] (-> real)
            re = bb.y ? -1.f : 1.f;
            im = bb.x ? -1.f : 1.f;
        }
        s_sym[s] = make_float2(re, im);
    }
    __syncthreads();

    // This thread's fixed phase quad: p0..p0+3, p0 in {0,4,8,12}.
    const int p0   = (4 * tid) & 15;
    const int flag = (p0 >= 8) ? 1 : 0;       // same for all 4 phases in quad
    const int k00  = (71 - p0) & 15;          // 7, 3, 15, 11; k0(p0+d) = k00 - d

    // Taps -> registers, duplicated for f32x2: t2[d][i] = rrc[k00-d+16i]
    ull t2[4][8];
    #pragma unroll
    for (int d = 0; d < 4; d++) {
        #pragma unroll
        for (int i = 0; i < 8; i++) {
            float t = s_rrc[(k00 - d) + 16 * i];
            t2[d][i] = pack2(t, t);
        }
    }

    const ull* s_sym64 = (const ull*)s_sym;
    ull* out_base = out2 + (long long)row * UP_LEN + (long long)tile * OUTS_PER_BLOCK;

    #pragma unroll
    for (int it = 0; it < 2; it++) {
        const int g     = it * THREADS + tid;            // 0..511 (quad index)
        const int sbase = it * 64 + (tid >> 2) + flag;   // shared symbol window

        ull acc0 = 0ULL, acc1 = 0ULL, acc2 = 0ULL, acc3 = 0ULL;
        #pragma unroll
        for (int i = 0; i < 8; i++) {
            ull s2 = s_sym64[sbase + i];
            fma2(acc0, t2[0][i], s2);
            fma2(acc1, t2[1][i], s2);
            fma2(acc2, t2[2][i], s2);
            fma2(acc3, t2[3][i], s2);
        }

        ull* dst = out_base + 4 * g;     // 4 consecutive complex outputs
        stcs2(dst,     acc0, acc1);
        stcs2(dst + 2, acc2, acc3);
    }
}

extern "C" void kernel_launch(void* const* d_in, const int* in_sizes, int n_in,
                              void* d_out, int out_size)
{
    const int*   bits = (const int*)d_in[0];
    const float* rrc  = (const float*)d_in[1];
    ull*         out  = (ull*)d_out;

    dim3 grid(UP_LEN / OUTS_PER_BLOCK, B_ROWS);   // (64, 256)
    qpsk_mod_kernel<<<grid, THREADS>>>(bits, rrc, out);
}

// round 4
// speedup vs baseline: 1.3304x; 1.3304x over previous
#include <cuda_runtime.h>

// QPSK modulator: bits (256,16384) int32 -> Gray QPSK -> x16 zero-stuff
// (offset 8) -> RRC (K=128) -> out (256, 131072, 2) float32.
//
// Polyphase: y[16q+p] = sum_{i=0..7} sym[q+jmin+i] * rrc[k0+16i],
//   k0 = (71-p)&15, jmin = (p<=7) ? -4 : -3, scaled by sqrt(16).
// sqrt(16)/sqrt(2) folded into taps so symbols are +-1.
//
// R4: thread owns phase pair (p0, p0+1), p0 = 2*(tid&7), and computes TWO
// adjacent symbol slots (windows offset by 1): 9 symbol LDS.64 + 8 tap
// LDS.128 (taps pre-duplicated (t,t); odd/even k0 adjacent -> one aligned
// 16B load gives both phases) feed 4 complex outputs via 32 FFMA2.
// No persistent tap registers -> high occupancy (R3 lesson).

#define B_ROWS     256
#define NUM_BITS   16384
#define NS         8192
#define SPS        16
#define UP_LEN     (NS * SPS)
#define K_TAPS     128

#define SYMS_PER_BLOCK   128
#define OUTS_PER_BLOCK   (SYMS_PER_BLOCK * SPS)   // 2048 complex
#define THREADS          256
#define HALO_L           4
#define SYM_TILE         (SYMS_PER_BLOCK + 8)     // 136

typedef unsigned long long ull;

__device__ __forceinline__ ull pack2(float lo, float hi) {
    ull v;
    asm("mov.b64 %0, {%1, %2};" : "=l"(v) : "f"(lo), "f"(hi));
    return v;
}

__device__ __forceinline__ void fma2(ull& acc, ull a, ull b) {
    asm("fma.rn.f32x2 %0, %1, %2, %0;" : "+l"(acc) : "l"(a), "l"(b));
}

__global__ __launch_bounds__(THREADS)
void qpsk_mod_kernel(const int* __restrict__ bits,
                     const float* __restrict__ rrc,
                     ulonglong2* __restrict__ out4)  // 16B = one phase-pair (re,im,re,im)
{
    __shared__ __align__(16) ull s_taps2[K_TAPS];   // (t,t) duplicated taps
    __shared__ float2 s_sym[SYM_TILE];

    const int tid  = threadIdx.x;
    const int tile = blockIdx.x;          // 0..63
    const int row  = blockIdx.y;          // 0..255
    const int q0   = tile * SYMS_PER_BLOCK;

    // Stage taps, pre-scaled by sqrt(SPS)/sqrt(2) = 2*sqrt(2), duplicated.
    if (tid < K_TAPS) {
        float t = rrc[tid] * 2.82842712474619f;
        s_taps2[tid] = pack2(t, t);
    }

    // Stage symbols (+-1) with halo; zero outside [0, NS)
    const int2* bits2 = (const int2*)(bits + (long long)row * NUM_BITS);
    for (int s = tid; s < SYM_TILE; s += THREADS) {
        int g = q0 - HALO_L + s;
        float re = 0.f, im = 0.f;
        if (g >= 0 && g < NS) {
            int2 bb = bits2[g];   // bb.x = bits[2g] (-> imag), bb.y = bits[2g+1] (-> real)
            re = bb.y ? -1.f : 1.f;
            im = bb.x ? -1.f : 1.f;
        }
        s_sym[s] = make_float2(re, im);
    }
    __syncthreads();

    // Fixed phase pair: p0 = 2*l (even), p0+1 (odd), l = tid & 7.
    const int l    = tid & 7;
    const int grp  = tid >> 3;            // 0..31
    const int flag = (l >= 4) ? 1 : 0;    // (p0 >= 8), same for both phases
    const int k0e  = (71 - 2 * l) & 15;   // odd in {7,5,3,1,15,13,11,9}
    const int k0o  = k0e - 1;             // even -> 16B-aligned pair base

    const ulonglong2* taps128 = (const ulonglong2*)s_taps2;  // pairs (2k, 2k+1)
    const int tp0 = k0o >> 1;             // pair index; +8 per tap row

    const ull* s_sym64 = (const ull*)s_sym;
    ulonglong2* out_base =
        out4 + (((long long)row * UP_LEN + (long long)tile * OUTS_PER_BLOCK) >> 1);

    #pragma unroll
    for (int it = 0; it < 2; it++) {
        const int pia   = it * 512 + 16 * grp + l;        // pair index, slot a
        const int sbase = it * 64 + 2 * grp + flag;       // window start, slot a

        ull acc_ae = 0ULL, acc_ao = 0ULL;   // slot a: even/odd phase
        ull acc_be = 0ULL, acc_bo = 0ULL;   // slot b (window +1)

        ull sa = s_sym64[sbase];
        #pragma unroll
        for (int i = 0; i < 8; i++) {
            ulonglong2 tp = taps128[tp0 + 8 * i];  // .x = odd-phase tap, .y = even-phase tap
            ull sb = s_sym64[sbase + i + 1];
            fma2(acc_ae, tp.y, sa);
            fma2(acc_ao, tp.x, sa);
            fma2(acc_be, tp.y, sb);
            fma2(acc_bo, tp.x, sb);
            sa = sb;
        }

        ulonglong2 oa; oa.x = acc_ae; oa.y = acc_ao;
        ulonglong2 ob; ob.x = acc_be; ob.y = acc_bo;
        out_base[pia]     = oa;
        out_base[pia + 8] = ob;
    }
}

extern "C" void kernel_launch(void* const* d_in, const int* in_sizes, int n_in,
                              void* d_out, int out_size)
{
    const int*   bits = (const int*)d_in[0];
    const float* rrc  = (const float*)d_in[1];
    ulonglong2*  out  = (ulonglong2*)d_out;

    dim3 grid(UP_LEN / OUTS_PER_BLOCK, B_ROWS);   // (64, 256)
    qpsk_mod_kernel<<<grid, THREADS>>>(bits, rrc, out);
}

// round 5
// speedup vs baseline: 1.6621x; 1.2494x over previous
#include <cuda_runtime.h>

// QPSK modulator: bits (256,16384) int32 -> Gray QPSK -> x16 zero-stuff
// (offset 8) -> RRC (K=128) -> out (256, 131072, 2) float32.
//
// Polyphase: y[16q+p] = sum_{i=0..7} sym[q+jmin+i] * rrc[k0+16i],
//   k0 = (71-p)&15, jmin = (p<=7) ? -4 : -3, scaled by sqrt(16).
// Symbols are +-1/sqrt2 -> fold sqrt(16)/sqrt(2) into taps; each output is
// a sum of 8 signed taps -> only 256 values per phase. Precompute
// T[pair][pattern] (float2 = even/odd phase) once in a tiny kernel, then the
// main kernel is: ballot sign bits -> funnel-shift 8-bit window pattern ->
// 2x LDS.64 table lookups -> STG.128. Zero FMA, ~2x fewer issue slots and
// L1 wavefronts than R2, regs ~30 (R3/R4 lesson: occupancy is king).
// Edge outputs (windows touching zero-padded halo) recomputed exactly
// in-block for the first/last 64 outputs of each row.

#define B_ROWS     256
#define NUM_BITS   16384
#define NS         8192
#define SPS        16
#define UP_LEN     (NS * SPS)      // 131072
#define SCALE      2.82842712474619f   // sqrt(16)/sqrt(2)

#define SYMS_PER_BLOCK   512
#define OUTS_PER_BLOCK   (SYMS_PER_BLOCK * SPS)   // 8192 complex
#define THREADS          256
#define ITS              16        // pairs per thread
#define TILES            (UP_LEN / OUTS_PER_BLOCK)  // 16
#define TROW             257       // padded table row stride (bank-conflict-free)
#define NWORDS           18        // 520 sign bits -> 17 words + 1 pad

typedef unsigned long long ull;

__device__ float2 g_tab2[8 * TROW];

__device__ __forceinline__ ull pack2(float lo, float hi) {
    ull v;
    asm("mov.b64 %0, {%1, %2};" : "=l"(v) : "f"(lo), "f"(hi));
    return v;
}

// ---------------------------------------------------------------- build table
__global__ void build_table_kernel(const float* __restrict__ rrc) {
    int pp = blockIdx.x;       // phase pair 0..7 -> phases (2pp, 2pp+1)
    int b  = threadIdx.x;      // sign pattern 0..255 (+ pad writer 256)
    if (b == 256) { g_tab2[pp * TROW + 256] = make_float2(0.f, 0.f); return; }
    int k0e = (71 - 2 * pp) & 15;   // odd, >= 1
    int k0o = k0e - 1;
    float se = 0.f, so = 0.f;
    #pragma unroll
    for (int i = 0; i < 8; i++) {
        float te = rrc[k0e + 16 * i] * SCALE;
        float to = rrc[k0o + 16 * i] * SCALE;
        float sg = ((b >> i) & 1) ? -1.f : 1.f;
        se = fmaf(sg, te, se);
        so = fmaf(sg, to, so);
    }
    g_tab2[pp * TROW + b] = make_float2(se, so);
}

// ---------------------------------------------------------------- main kernel
__global__ __launch_bounds__(THREADS)
void qpsk_mod_kernel(const int* __restrict__ bits,
                     const float* __restrict__ rrc,
                     ulonglong2* __restrict__ out4)
{
    __shared__ __align__(16) float2 s_tab[8 * TROW];
    __shared__ unsigned s_wre[NWORDS], s_wim[NWORDS];

    const int tid  = threadIdx.x;
    const int tile = blockIdx.x;       // 0..15
    const int row  = blockIdx.y;       // 0..255
    const int q0   = tile * SYMS_PER_BLOCK;

    // Copy lookup table gmem -> smem (1028 float4 = 16448 B, L2-resident)
    {
        const float4* src = (const float4*)g_tab2;
        float4*       dst = (float4*)s_tab;
        #pragma unroll
        for (int k = 0; k < 5; k++) {
            int i = k * THREADS + tid;
            if (i < 1028) dst[i] = src[i];
        }
    }

    // Stage sign bits via ballot: word w holds bits of symbols 32w..32w+31
    // (local index t <-> symbol g = q0-4+t; out-of-range -> bit 0 = +1,
    //  fixed up at the row edges below).
    const int2* bits2 = (const int2*)(bits + (long long)row * NUM_BITS);
    const unsigned lane = tid & 31;
    #pragma unroll
    for (int k = 0; k < 3; k++) {
        int t = k * THREADS + tid;
        int g = q0 - 4 + t;
        bool valid = (t < SYMS_PER_BLOCK + 8) && (g >= 0) && (g < NS);
        int2 bb = make_int2(0, 0);
        if (valid) bb = bits2[g];
        unsigned mre = __ballot_sync(0xFFFFFFFFu, valid && (bb.y & 1));
        unsigned mim = __ballot_sync(0xFFFFFFFFu, valid && (bb.x & 1));
        int wi = t >> 5;
        if (lane == 0 && wi < NWORDS) { s_wre[wi] = mre; s_wim[wi] = mim; }
    }
    __syncthreads();

    // Thread owns fixed phase pair (2l, 2l+1); iterates over symbol windows.
    const int l    = tid & 7;
    const int grp  = tid >> 3;                    // 0..31
    const int flag = (l >= 4) ? 1 : 0;            // (phase >= 8)
    const float2* tabp = s_tab + l * TROW;
    ulonglong2* out_base =
        out4 + (((long long)row * UP_LEN + (long long)tile * OUTS_PER_BLOCK) >> 1);

    #pragma unroll
    for (int it = 0; it < ITS; it++) {
        int pi = it * THREADS + tid;              // pair index 0..4095
        int w  = it * 32 + grp + flag;            // window start bit
        int wi = w >> 5, sh = w & 31;
        unsigned pre = __funnelshift_r(s_wre[wi], s_wre[wi + 1], sh) & 0xFF;
        unsigned pim = __funnelshift_r(s_wim[wi], s_wim[wi + 1], sh) & 0xFF;
        float2 vr = tabp[pre];                    // (re_even, re_odd)
        float2 vi = tabp[pim];                    // (im_even, im_odd)
        ulonglong2 o;
        o.x = pack2(vr.x, vi.x);
        o.y = pack2(vr.y, vi.y);
        out_base[pi] = o;
    }

    // Edge fixup: windows that touch symbols outside [0,NS) assumed +1 above;
    // true value uses 0. Contaminated outputs: q<=3 (n<64) and q>=NS-4
    // (n >= UP_LEN-64). Recompute exactly, overwrite after syncthreads.
    if (tile == 0 || tile == TILES - 1) {
        __syncthreads();
        if (tid < 64) {
            int n = (tile == 0) ? tid : (UP_LEN - 64 + tid);
            int p = n & 15, q = n >> 4;
            int k0   = (71 - p) & 15;
            int jmin = (p <= 7) ? -4 : -3;
            float re = 0.f, im = 0.f;
            #pragma unroll
            for (int i = 0; i < 8; i++) {
                int g = q + jmin + i;
                if ((unsigned)g < (unsigned)NS) {
                    int2 bb = bits2[g];
                    float t = rrc[k0 + 16 * i] * SCALE;
                    re += (bb.y & 1) ? -t : t;
                    im += (bb.x & 1) ? -t : t;
                }
            }
            ull* out2 = (ull*)out4;
            out2[(long long)row * UP_LEN + n] = pack2(re, im);
        }
    }
}

extern "C" void kernel_launch(void* const* d_in, const int* in_sizes, int n_in,
                              void* d_out, int out_size)
{
    const int*   bits = (const int*)d_in[0];
    const float* rrc  = (const float*)d_in[1];
    ulonglong2*  out  = (ulonglong2*)d_out;

    build_table_kernel<<<8, 257>>>(rrc);
    dim3 grid(TILES, B_ROWS);                 // (16, 256)
    qpsk_mod_kernel<<<grid, THREADS>>>(bits, rrc, out);
}

// round 6
// speedup vs baseline: 1.6740x; 1.0072x over previous
#include <cuda_runtime.h>

// QPSK modulator: bits (256,16384) int32 -> Gray QPSK -> x16 zero-stuff
// (offset 8) -> RRC (K=128) -> out (256, 131072, 2) float32.
//
// Polyphase: y[16q+p] = sum_{i=0..7} sym[q+jmin+i] * rrc[k0+16i],
//   k0 = (71-p)&15, jmin = (p<=7) ? -4 : -3, scaled by sqrt(16).
// Symbols are +-1/sqrt2 -> fold sqrt(16)/sqrt(2) into taps; each output is a
// sum of 8 signed taps -> 256 possible values per phase. Each block builds
// the 8x256 float2 lookup table (even/odd phase per entry) in its prologue
// (cheap, overlapped), stages sign bits via ballot, then the mainloop is:
// funnel-shift 8-bit pattern -> 2x LDS.64 -> STG.128. Zero mainloop FMA.
// R6 vs R5: single launch (no build kernel, no 67MB L2 table re-read),
// forced <=32 regs for full occupancy (R3/R4 lesson: warps are king).

#define B_ROWS     256
#define NUM_BITS   16384
#define NS         8192
#define SPS        16
#define UP_LEN     (NS * SPS)          // 131072
#define SCALE      2.82842712474619f   // sqrt(16)/sqrt(2)

#define SYMS_PER_BLOCK   512
#define OUTS_PER_BLOCK   (SYMS_PER_BLOCK * SPS)     // 8192 complex
#define THREADS          256
#define ITS              16
#define TILES            (UP_LEN / OUTS_PER_BLOCK)  // 16
#define TROW             257                        // padded row stride
#define NWORDS           18                         // 520 sign bits

typedef unsigned long long ull;

__device__ __forceinline__ ull pack2(float lo, float hi) {
    ull v;
    asm("mov.b64 %0, {%1, %2};" : "=l"(v) : "f"(lo), "f"(hi));
    return v;
}

__global__ __launch_bounds__(THREADS, 8)
void qpsk_mod_kernel(const int* __restrict__ bits,
                     const float* __restrict__ rrc,
                     ulonglong2* __restrict__ out4)
{
    __shared__ __align__(16) float2 s_tab[8 * TROW];
    __shared__ unsigned s_wre[NWORDS], s_wim[NWORDS];

    const int tid  = threadIdx.x;
    const int tile = blockIdx.x;       // 0..15
    const int row  = blockIdx.y;       // 0..255
    const int q0   = tile * SYMS_PER_BLOCK;

    // ---- Build lookup table in-block: thread t fills row (t>>5), patterns
    // lane, lane+32, ..., lane+224. Taps load as warp-wide LDG broadcasts.
    {
        const int r    = tid >> 5;          // phase-pair row 0..7
        const int lane = tid & 31;
        const int k0e  = (71 - 2 * r) & 15; // odd
        const int k0o  = k0e - 1;
        float te[8], to[8];
        #pragma unroll
        for (int i = 0; i < 8; i++) {
            te[i] = __ldg(rrc + k0e + 16 * i) * SCALE;
            to[i] = __ldg(rrc + k0o + 16 * i) * SCALE;
        }
        #pragma unroll
        for (int j = 0; j < 8; j++) {
            int b = lane + 32 * j;
            float se = 0.f, so = 0.f;
            #pragma unroll
            for (int i = 0; i < 8; i++) {
                float sg = ((b >> i) & 1) ? -1.f : 1.f;
                se = fmaf(sg, te[i], se);
                so = fmaf(sg, to[i], so);
            }
            s_tab[r * TROW + b] = make_float2(se, so);
        }
    }

    // ---- Stage sign bits via ballot: word w holds symbols 32w..32w+31
    // (local t <-> symbol g = q0-4+t; out-of-range -> +1, fixed up below).
    const int2* bits2 = (const int2*)(bits + (long long)row * NUM_BITS);
    const unsigned lane = tid & 31;
    #pragma unroll
    for (int k = 0; k < 3; k++) {
        int t = k * THREADS + tid;
        int g = q0 - 4 + t;
        bool valid = (t < SYMS_PER_BLOCK + 8) && (g >= 0) && (g < NS);
        int2 bb = make_int2(0, 0);
        if (valid) bb = bits2[g];
        unsigned mre = __ballot_sync(0xFFFFFFFFu, valid && (bb.y & 1));
        unsigned mim = __ballot_sync(0xFFFFFFFFu, valid && (bb.x & 1));
        int wi = t >> 5;
        if (lane == 0 && wi < NWORDS) { s_wre[wi] = mre; s_wim[wi] = mim; }
    }
    __syncthreads();

    // ---- Main loop: fixed phase pair (2l, 2l+1) per thread.
    const int l    = tid & 7;
    const int grp  = tid >> 3;                 // 0..31
    const int flag = (l >= 4) ? 1 : 0;         // (phase >= 8)
    const float2* tabp = s_tab + l * TROW;
    ulonglong2* out_base =
        out4 + (((long long)row * UP_LEN + (long long)tile * OUTS_PER_BLOCK) >> 1);

    #pragma unroll
    for (int it = 0; it < ITS; it++) {
        int pi = it * THREADS + tid;           // pair index 0..4095
        int w  = it * 32 + grp + flag;         // window start bit
        int wi = w >> 5, sh = w & 31;
        unsigned pre = __funnelshift_r(s_wre[wi], s_wre[wi + 1], sh) & 0xFF;
        unsigned pim = __funnelshift_r(s_wim[wi], s_wim[wi + 1], sh) & 0xFF;
        float2 vr = tabp[pre];                 // (re_even, re_odd)
        float2 vi = tabp[pim];                 // (im_even, im_odd)
        ulonglong2 o;
        o.x = pack2(vr.x, vi.x);
        o.y = pack2(vr.y, vi.y);
        out_base[pi] = o;
    }

    // ---- Edge fixup: windows touching symbols outside [0,NS) assumed +1;
    // true value uses 0. Contaminated: n<64 and n>=UP_LEN-64. Recompute.
    if (tile == 0 || tile == TILES - 1) {
        __syncthreads();
        if (tid < 64) {
            int n = (tile == 0) ? tid : (UP_LEN - 64 + tid);
            int p = n & 15, q = n >> 4;
            int k0   = (71 - p) & 15;
            int jmin = (p <= 7) ? -4 : -3;
            float re = 0.f, im = 0.f;
            #pragma unroll
            for (int i = 0; i < 8; i++) {
                int g = q + jmin + i;
                if ((unsigned)g < (unsigned)NS) {
                    int2 bb = bits2[g];
                    float t = __ldg(rrc + k0 + 16 * i) * SCALE;
                    re += (bb.y & 1) ? -t : t;
                    im += (bb.x & 1) ? -t : t;
                }
            }
            ull* out2 = (ull*)out4;
            out2[(long long)row * UP_LEN + n] = pack2(re, im);
        }
    }
}

extern "C" void kernel_launch(void* const* d_in, const int* in_sizes, int n_in,
                              void* d_out, int out_size)
{
    const int*   bits = (const int*)d_in[0];
    const float* rrc  = (const float*)d_in[1];
    ulonglong2*  out  = (ulonglong2*)d_out;

    dim3 grid(TILES, B_ROWS);                 // (16, 256)
    qpsk_mod_kernel<<<grid, THREADS>>>(bits, rrc, out);
}

// round 7
// speedup vs baseline: 1.9869x; 1.1869x over previous
#include <cuda_runtime.h>

// QPSK modulator: bits (256,16384) int32 -> Gray QPSK -> x16 zero-stuff
// (offset 8) -> RRC (K=128) -> out (256, 131072, 2) float32.
//
// Polyphase: y[16q+p] = sum_{i=0..7} sym[q+jmin+i] * rrc[k0+16i],
//   k0 = (71-p)&15, jmin = (p<=7) ? -4 : -3, scaled by sqrt(16).
// Symbols are +-1/sqrt2 -> fold sqrt(16)/sqrt(2) into taps; each output is a
// sum of 8 signed taps -> 256 possible values per phase. Each block builds
// the 8x256 float2 lookup table in its prologue, stages sign bits via
// ballot, then the mainloop is: funnel-shift 8-bit pattern -> 2x LDS.64 ->
// streaming STG.128.
// R7 vs R6: st.global.cs (evict-first) on the output. Bench timing is
// steady-state DRAM *write* throughput (L2 holds ~half the 268MB output at
// kernel end; drain lands in the next replay) -> make the writebacks start
// during the kernel instead of after it.

#define B_ROWS     256
#define NUM_BITS   16384
#define NS         8192
#define SPS        16
#define UP_LEN     (NS * SPS)          // 131072
#define SCALE      2.82842712474619f   // sqrt(16)/sqrt(2)

#define SYMS_PER_BLOCK   512
#define OUTS_PER_BLOCK   (SYMS_PER_BLOCK * SPS)     // 8192 complex
#define THREADS          256
#define ITS              16
#define TILES            (UP_LEN / OUTS_PER_BLOCK)  // 16
#define TROW             257                        // padded row stride
#define NWORDS           18                         // 520 sign bits

typedef unsigned long long ull;

__device__ __forceinline__ ull pack2(float lo, float hi) {
    ull v;
    asm("mov.b64 %0, {%1, %2};" : "=l"(v) : "f"(lo), "f"(hi));
    return v;
}

__device__ __forceinline__ void stcs2(ulonglong2* p, ull lo, ull hi) {
    asm volatile("st.global.cs.v2.u64 [%0], {%1, %2};"
                 :: "l"(p), "l"(lo), "l"(hi) : "memory");
}

__device__ __forceinline__ void stcs1(ull* p, ull v) {
    asm volatile("st.global.cs.u64 [%0], %1;" :: "l"(p), "l"(v) : "memory");
}

__global__ __launch_bounds__(THREADS, 8)
void qpsk_mod_kernel(const int* __restrict__ bits,
                     const float* __restrict__ rrc,
                     ulonglong2* __restrict__ out4)
{
    __shared__ __align__(16) float2 s_tab[8 * TROW];
    __shared__ unsigned s_wre[NWORDS], s_wim[NWORDS];

    const int tid  = threadIdx.x;
    const int tile = blockIdx.x;       // 0..15
    const int row  = blockIdx.y;       // 0..255
    const int q0   = tile * SYMS_PER_BLOCK;

    // ---- Build lookup table in-block: thread t fills row (t>>5), patterns
    // lane, lane+32, ..., lane+224. Taps load as warp-wide LDG broadcasts.
    {
        const int r    = tid >> 5;          // phase-pair row 0..7
        const int lane = tid & 31;
        const int k0e  = (71 - 2 * r) & 15; // odd
        const int k0o  = k0e - 1;
        float te[8], to[8];
        #pragma unroll
        for (int i = 0; i < 8; i++) {
            te[i] = __ldg(rrc + k0e + 16 * i) * SCALE;
            to[i] = __ldg(rrc + k0o + 16 * i) * SCALE;
        }
        #pragma unroll
        for (int j = 0; j < 8; j++) {
            int b = lane + 32 * j;
            float se = 0.f, so = 0.f;
            #pragma unroll
            for (int i = 0; i < 8; i++) {
                float sg = ((b >> i) & 1) ? -1.f : 1.f;
                se = fmaf(sg, te[i], se);
                so = fmaf(sg, to[i], so);
            }
            s_tab[r * TROW + b] = make_float2(se, so);
        }
    }

    // ---- Stage sign bits via ballot: word w holds symbols 32w..32w+31
    // (local t <-> symbol g = q0-4+t; out-of-range -> +1, fixed up below).
    const int2* bits2 = (const int2*)(bits + (long long)row * NUM_BITS);
    const unsigned lane = tid & 31;
    #pragma unroll
    for (int k = 0; k < 3; k++) {
        int t = k * THREADS + tid;
        int g = q0 - 4 + t;
        bool valid = (t < SYMS_PER_BLOCK + 8) && (g >= 0) && (g < NS);
        int2 bb = make_int2(0, 0);
        if (valid) bb = bits2[g];
        unsigned mre = __ballot_sync(0xFFFFFFFFu, valid && (bb.y & 1));
        unsigned mim = __ballot_sync(0xFFFFFFFFu, valid && (bb.x & 1));
        int wi = t >> 5;
        if (lane == 0 && wi < NWORDS) { s_wre[wi] = mre; s_wim[wi] = mim; }
    }
    __syncthreads();

    // ---- Main loop: fixed phase pair (2l, 2l+1) per thread.
    const int l    = tid & 7;
    const int grp  = tid >> 3;                 // 0..31
    const int flag = (l >= 4) ? 1 : 0;         // (phase >= 8)
    const float2* tabp = s_tab + l * TROW;
    ulonglong2* out_base =
        out4 + (((long long)row * UP_LEN + (long long)tile * OUTS_PER_BLOCK) >> 1);

    #pragma unroll
    for (int it = 0; it < ITS; it++) {
        int pi = it * THREADS + tid;           // pair index 0..4095
        int w  = it * 32 + grp + flag;         // window start bit
        int wi = w >> 5, sh = w & 31;
        unsigned pre = __funnelshift_r(s_wre[wi], s_wre[wi + 1], sh) & 0xFF;
        unsigned pim = __funnelshift_r(s_wim[wi], s_wim[wi + 1], sh) & 0xFF;
        float2 vr = tabp[pre];                 // (re_even, re_odd)
        float2 vi = tabp[pim];                 // (im_even, im_odd)
        stcs2(out_base + pi, pack2(vr.x, vi.x), pack2(vr.y, vi.y));
    }

    // ---- Edge fixup: windows touching symbols outside [0,NS) assumed +1;
    // true value uses 0. Contaminated: n<64 and n>=UP_LEN-64. Recompute.
    if (tile == 0 || tile == TILES - 1) {
        __syncthreads();
        if (tid < 64) {
            int n = (tile == 0) ? tid : (UP_LEN - 64 + tid);
            int p = n & 15, q = n >> 4;
            int k0   = (71 - p) & 15;
            int jmin = (p <= 7) ? -4 : -3;
            float re = 0.f, im = 0.f;
            #pragma unroll
            for (int i = 0; i < 8; i++) {
                int g = q + jmin + i;
                if ((unsigned)g < (unsigned)NS) {
                    int2 bb = bits2[g];
                    float t = __ldg(rrc + k0 + 16 * i) * SCALE;
                    re += (bb.y & 1) ? -t : t;
                    im += (bb.x & 1) ? -t : t;
                }
            }
            ull* out2 = (ull*)out4;
            stcs1(out2 + (long long)row * UP_LEN + n, pack2(re, im));
        }
    }
}

extern "C" void kernel_launch(void* const* d_in, const int* in_sizes, int n_in,
                              void* d_out, int out_size)
{
    const int*   bits = (const int*)d_in[0];
    const float* rrc  = (const float*)d_in[1];
    ulonglong2*  out  = (ulonglong2*)d_out;

    dim3 grid(TILES, B_ROWS);                 // (16, 256)
    qpsk_mod_kernel<<<grid, THREADS>>>(bits, rrc, out);
}